// round 1
// baseline (speedup 1.0000x reference)
#include <cuda_runtime.h>
#include <math.h>

// Static problem sizes
#define NHH  8
#define HDD  4
#define BB   4
#define HH   32
#define WW   32
#define MM   21
#define CC   32
#define NN   1024        // H*W
#define DD   84          // M*hd
#define BH   32          // B*NH
#define ROWS 86016       // B_*M = 4096*21

// ---- scratch (device globals; no runtime allocation) ----
__device__ float g_q[BH * NN * DD];           // 11 MB
__device__ float g_k[BH * NN * DD];
__device__ float g_v[BH * NN * DD];
__device__ float g_x2[BH * NN];
__device__ float g_pool[BH];
__device__ float g_xw[NHH * NN];
__device__ float g_xp[NHH * NN];
__device__ float g_table[NHH * 63 * 63];
__device__ float g_S[(size_t)BH * NN * NN];   // 134 MB probs
__device__ float g_opre[(size_t)ROWS * CC];   // 11 MB

// ---------------------------------------------------------------------------
// K1: qkv = x @ W_qkv + b_qkv, scattered to (b,h,n,m*hd) layout per q/k/v
// ---------------------------------------------------------------------------
__global__ void k_qkv(const float* __restrict__ x, const float* __restrict__ Wq,
                      const float* __restrict__ bq) {
    __shared__ float xs[32][33];
    __shared__ float ws[32][96];
    __shared__ float bs[96];
    int t = threadIdx.x;
    int row0 = blockIdx.x * 32;
    for (int i = t; i < 32 * 96; i += 256) ws[i / 96][i % 96] = Wq[i];
    if (t < 96) bs[t] = bq[t];
    for (int i = t; i < 32 * 32; i += 256)
        xs[i >> 5][i & 31] = x[(size_t)row0 * 32 + i];
    __syncthreads();
    for (int idx = t; idx < 32 * 96; idx += 256) {
        int r = idx / 96, j = idx % 96;
        float acc = bs[j];
#pragma unroll
        for (int kk = 0; kk < 32; kk++) acc += xs[r][kk] * ws[kk][j];
        int R = row0 + r;
        int b_ = R / 21, m = R % 21;
        int b = b_ >> 10, n = b_ & 1023;
        int which = j >> 5;
        int hc = j & 31;
        int h = hc >> 2, c = hc & 3;
        size_t dst = ((size_t)(b * NHH + h) * NN + n) * DD + m * 4 + c;
        float* g = (which == 0) ? g_q : ((which == 1) ? g_k : g_v);
        g[dst] = acc;
    }
}

// ---------------------------------------------------------------------------
// K2: x2[b,h,n] = sum_{m,c} x[b*N+n, m, h*4+c] * W_sq[m*4+c] + b_sq
// ---------------------------------------------------------------------------
__global__ void k_x2(const float* __restrict__ x, const float* __restrict__ Wsq,
                     const float* __restrict__ bsq) {
    __shared__ float w[DD];
    int t = threadIdx.x;
    if (t < DD) w[t] = Wsq[t];
    __syncthreads();
    int gid = blockIdx.x * blockDim.x + t;
    if (gid >= BH * NN) return;
    int n = gid & 1023;
    int bh = gid >> 10;
    int h = bh & 7, b = bh >> 3;
    const float* xr = x + (size_t)(b * NN + n) * (MM * CC) + h * 4;
    float acc = bsq[0];
#pragma unroll
    for (int m = 0; m < MM; m++)
#pragma unroll
        for (int c = 0; c < 4; c++) acc += xr[m * 32 + c] * w[m * 4 + c];
    g_x2[gid] = acc;
}

// ---------------------------------------------------------------------------
// K3: pooled scalar per (b,h) = mean + max over spatial
// ---------------------------------------------------------------------------
__global__ void k_pool() {
    int bh = blockIdx.x;
    int t = threadIdx.x;
    const float* p = g_x2 + (size_t)bh * NN;
    float s = 0.f, mx = -1e30f;
    for (int i = t; i < NN; i += 256) { float v = p[i]; s += v; mx = fmaxf(mx, v); }
    __shared__ float ss[256], smx[256];
    ss[t] = s; smx[t] = mx;
    __syncthreads();
    for (int o = 128; o > 0; o >>= 1) {
        if (t < o) { ss[t] += ss[t + o]; smx[t] = fmaxf(smx[t], smx[t + o]); }
        __syncthreads();
    }
    if (t == 0) g_pool[bh] = ss[0] * (1.0f / 1024.0f) + smx[0];
}

// ---------------------------------------------------------------------------
// K4: depthwise conv + pooled, mean over batch -> x_weight (s=0) / x_proj (s=1)
//   out channel o = s*8+h reads input channel o/2; pooled uses channel h
// ---------------------------------------------------------------------------
__global__ void k_spatial(const float* __restrict__ Wdw, const float* __restrict__ bdw) {
    int sb = blockIdx.x >> 3, h = blockIdx.x & 7;
    int o = sb * 8 + h, ic = o >> 1;
    __shared__ float xs[NN];
    __shared__ float wk[9];
    int t = threadIdx.x;
    if (t < 9) wk[t] = Wdw[o * 9 + t];
    float acc[4] = {0.f, 0.f, 0.f, 0.f};
    float scal = 0.f;
    for (int b = 0; b < 4; b++) {
        __syncthreads();
        for (int i = t; i < NN; i += 256) xs[i] = g_x2[(size_t)(b * 8 + ic) * NN + i];
        __syncthreads();
        scal += g_pool[b * 8 + h];
#pragma unroll
        for (int qq = 0; qq < 4; qq++) {
            int pix = qq * 256 + t;
            int y = pix >> 5, xx = pix & 31;
            float s = 0.f;
#pragma unroll
            for (int dy = -1; dy <= 1; dy++)
#pragma unroll
                for (int dx = -1; dx <= 1; dx++) {
                    int yy = y + dy, xq = xx + dx;
                    if (yy >= 0 && yy < 32 && xq >= 0 && xq < 32)
                        s += xs[yy * 32 + xq] * wk[(dy + 1) * 3 + (dx + 1)];
                }
            acc[qq] += s;
        }
    }
    float bo = bdw[o];
    float* dst = sb ? g_xp : g_xw;
#pragma unroll
    for (int qq = 0; qq < 4; qq++) {
        int pix = qq * 256 + t;
        dst[h * NN + pix] = acc[qq] * 0.25f + bo + scal * 0.25f;
    }
}

// ---------------------------------------------------------------------------
// K5: table[h,i,j] = full-conv: sum_{a,b} x_proj[h,i-a,j-b] * x_weight[h,a,b]
// ---------------------------------------------------------------------------
__global__ void k_table() {
    int h = blockIdx.x;
    __shared__ float xp[NN], xw[NN];
    int t = threadIdx.x;
    for (int i = t; i < NN; i += 256) { xp[i] = g_xp[h * NN + i]; xw[i] = g_xw[h * NN + i]; }
    __syncthreads();
    for (int idx = t; idx < 63 * 63; idx += 256) {
        int i = idx / 63, j = idx % 63;
        int a0 = max(0, i - 31), a1 = min(31, i);
        int b0 = max(0, j - 31), b1 = min(31, j);
        float acc = 0.f;
        for (int a = a0; a <= a1; a++)
            for (int bb = b0; bb <= b1; bb++)
                acc += xp[(i - a) * 32 + (j - bb)] * xw[a * 32 + bb];
        g_table[h * 3969 + idx] = acc;
    }
}

// ---------------------------------------------------------------------------
// K6: S = scale * Q @ K^T + rel_bias    (128x128 tiles, 8x8 micro)
// ---------------------------------------------------------------------------
__global__ void __launch_bounds__(256, 2) k_qk() {
    extern __shared__ float smem_buf[];
    float* Qs = smem_buf;            // [84][130]
    float* Ks = smem_buf + 84 * 130; // [84][130]
    int bh = blockIdx.z;
    int h = bh & 7;
    int rt = blockIdx.y * 128, ct = blockIdx.x * 128;
    int t = threadIdx.x;
    int tx = t & 15, ty = t >> 4;
    const float* qb = g_q + (size_t)bh * NN * DD;
    const float* kb = g_k + (size_t)bh * NN * DD;
    for (int i = t; i < 128 * 84; i += 256) {
        int r = i / 84, kk = i % 84;
        Qs[kk * 130 + r] = qb[(size_t)(rt + r) * DD + kk];
        Ks[kk * 130 + r] = kb[(size_t)(ct + r) * DD + kk];
    }
    __syncthreads();
    float acc[8][8] = {};
#pragma unroll 2
    for (int kk = 0; kk < 84; kk++) {
        float a[8], bb[8];
#pragma unroll
        for (int u = 0; u < 8; u++) a[u] = Qs[kk * 130 + ty * 8 + u];
#pragma unroll
        for (int v = 0; v < 8; v++) bb[v] = Ks[kk * 130 + tx * 8 + v];
#pragma unroll
        for (int u = 0; u < 8; u++)
#pragma unroll
            for (int v = 0; v < 8; v++) acc[u][v] += a[u] * bb[v];
    }
    const float scale = 0.03125f;  // N^-0.5 = 1/32
    const float* tab = g_table + h * 3969;
    float* Sp = g_S + (size_t)bh * NN * NN;
#pragma unroll
    for (int u = 0; u < 8; u++) {
        int i = rt + ty * 8 + u;
        int ri = i >> 5, ci = i & 31;
#pragma unroll
        for (int v = 0; v < 8; v++) {
            int j = ct + tx * 8 + v;
            int rj = j >> 5, cj = j & 31;
            float bias = tab[(ri - rj + 31) * 63 + (ci - cj + 31)];
            Sp[(size_t)i * NN + j] = acc[u][v] * scale + bias;
        }
    }
}

// ---------------------------------------------------------------------------
// K7: row softmax over S (in place), one block per row
// ---------------------------------------------------------------------------
__global__ void k_softmax() {
    int t = threadIdx.x;
    float* p = g_S + (size_t)blockIdx.x * NN;
    float4 v = ((float4*)p)[t];
    __shared__ float red[8];
    __shared__ float red2[8];
    float mx = fmaxf(fmaxf(v.x, v.y), fmaxf(v.z, v.w));
#pragma unroll
    for (int o = 16; o; o >>= 1) mx = fmaxf(mx, __shfl_xor_sync(0xffffffffu, mx, o));
    if ((t & 31) == 0) red[t >> 5] = mx;
    __syncthreads();
    if (t < 32) {
        float m = (t < 8) ? red[t] : -1e30f;
#pragma unroll
        for (int o = 4; o; o >>= 1) m = fmaxf(m, __shfl_xor_sync(0xffffffffu, m, o));
        if (t == 0) red[0] = m;
    }
    __syncthreads();
    float M = red[0];
    v.x = __expf(v.x - M); v.y = __expf(v.y - M);
    v.z = __expf(v.z - M); v.w = __expf(v.w - M);
    float s = v.x + v.y + v.z + v.w;
#pragma unroll
    for (int o = 16; o; o >>= 1) s += __shfl_xor_sync(0xffffffffu, s, o);
    if ((t & 31) == 0) red2[t >> 5] = s;
    __syncthreads();
    if (t < 32) {
        float m2 = (t < 8) ? red2[t] : 0.f;
#pragma unroll
        for (int o = 4; o; o >>= 1) m2 += __shfl_xor_sync(0xffffffffu, m2, o);
        if (t == 0) red2[0] = m2;
    }
    __syncthreads();
    float inv = 1.0f / red2[0];
    v.x *= inv; v.y *= inv; v.z *= inv; v.w *= inv;
    ((float4*)p)[t] = v;
}

// ---------------------------------------------------------------------------
// K8: O = P @ V  (64-row x 96-col tile, 4x6 micro), scatter to (b_,m,C) layout
// ---------------------------------------------------------------------------
__global__ void __launch_bounds__(256) k_pv() {
    __shared__ float Ps[64][65];
    __shared__ float Vs[64][97];
    int bh = blockIdx.z;
    int rt = blockIdx.y * 64;
    int t = threadIdx.x;
    int tx = t & 15, ty = t >> 4;
    const float* Sp = g_S + (size_t)bh * NN * NN;
    const float* vb = g_v + (size_t)bh * NN * DD;
    float acc[4][6] = {};
    for (int jc = 0; jc < NN; jc += 64) {
        __syncthreads();
        for (int i = t; i < 64 * 64; i += 256) {
            int r = i >> 6, j = i & 63;
            Ps[r][j] = Sp[(size_t)(rt + r) * NN + jc + j];
        }
        for (int i = t; i < 64 * 96; i += 256) {
            int j = i / 96, d = i % 96;
            Vs[j][d] = (d < DD) ? vb[(size_t)(jc + j) * DD + d] : 0.f;
        }
        __syncthreads();
#pragma unroll 4
        for (int j = 0; j < 64; j++) {
            float a[4], bb[6];
#pragma unroll
            for (int u = 0; u < 4; u++) a[u] = Ps[ty * 4 + u][j];
#pragma unroll
            for (int v = 0; v < 6; v++) bb[v] = Vs[j][tx * 6 + v];
#pragma unroll
            for (int u = 0; u < 4; u++)
#pragma unroll
                for (int v = 0; v < 6; v++) acc[u][v] += a[u] * bb[v];
        }
    }
    int b = bh >> 3, h = bh & 7;
#pragma unroll
    for (int u = 0; u < 4; u++) {
        int i = rt + ty * 4 + u;
#pragma unroll
        for (int v = 0; v < 6; v++) {
            int d = tx * 6 + v;
            if (d < DD) {
                int m = d >> 2, c = d & 3;
                g_opre[((size_t)((b << 10) + i) * MM + m) * CC + h * 4 + c] = acc[u][v];
            }
        }
    }
}

// ---------------------------------------------------------------------------
// K9: out = opre @ W_proj + b_proj
// ---------------------------------------------------------------------------
__global__ void k_proj(const float* __restrict__ Wp, const float* __restrict__ bp,
                       float* __restrict__ out) {
    __shared__ float xs[32][33];
    __shared__ float ws[32][32];
    __shared__ float bs[32];
    int t = threadIdx.x;
    int row0 = blockIdx.x * 32;
    for (int i = t; i < 1024; i += 256) ws[i >> 5][i & 31] = Wp[i];
    if (t < 32) bs[t] = bp[t];
    for (int i = t; i < 1024; i += 256) xs[i >> 5][i & 31] = g_opre[(size_t)row0 * 32 + i];
    __syncthreads();
    for (int idx = t; idx < 1024; idx += 256) {
        int r = idx >> 5, j = idx & 31;
        float acc = bs[j];
#pragma unroll
        for (int kk = 0; kk < 32; kk++) acc += xs[r][kk] * ws[kk][j];
        out[(size_t)(row0 + r) * 32 + j] = acc;
    }
}

// ---------------------------------------------------------------------------
extern "C" void kernel_launch(void* const* d_in, const int* in_sizes, int n_in,
                              void* d_out, int out_size) {
    (void)in_sizes; (void)n_in; (void)out_size;
    const float* x   = (const float*)d_in[0];
    const float* Wq  = (const float*)d_in[1];
    const float* bq  = (const float*)d_in[2];
    const float* Wp  = (const float*)d_in[3];
    const float* bp  = (const float*)d_in[4];
    const float* Wsq = (const float*)d_in[5];
    const float* bsq = (const float*)d_in[6];
    const float* Wdw = (const float*)d_in[7];
    const float* bdw = (const float*)d_in[8];
    float* out = (float*)d_out;

    static int init_done = 0;
    if (!init_done) {
        cudaFuncSetAttribute(k_qk, cudaFuncAttributeMaxDynamicSharedMemorySize,
                             2 * 84 * 130 * 4);
        init_done = 1;
    }

    k_qkv<<<ROWS / 32, 256>>>(x, Wq, bq);
    k_x2<<<(BH * NN) / 256, 256>>>(x, Wsq, bsq);
    k_pool<<<BH, 256>>>();
    k_spatial<<<16, 256>>>(Wdw, bdw);
    k_table<<<NHH, 256>>>();
    dim3 g1(8, 8, BH);
    k_qk<<<g1, 256, 2 * 84 * 130 * 4>>>();
    k_softmax<<<BH * NN, 256>>>();
    dim3 g2(1, 16, BH);
    k_pv<<<g2, 256>>>();
    k_proj<<<ROWS / 32, 256>>>(Wp, bp, out);
}

// round 3
// speedup vs baseline: 1.1458x; 1.1458x over previous
#include <cuda_runtime.h>
#include <cuda_bf16.h>
#include <math.h>
#include <stdint.h>

#define NHH  8
#define NN   1024
#define MM   21
#define CC   32
#define DD   84
#define BH   32
#define ROWS 86016

// ---- scratch (device globals) ----
__device__ __nv_bfloat16 g_qh[(size_t)BH * NN * 96];
__device__ __nv_bfloat16 g_ql[(size_t)BH * NN * 96];
__device__ __nv_bfloat16 g_kh[(size_t)BH * NN * 96];
__device__ __nv_bfloat16 g_kl[(size_t)BH * NN * 96];
__device__ __nv_bfloat16 g_vth[(size_t)BH * 96 * NN];   // [bh][d][n]
__device__ __nv_bfloat16 g_vtl[(size_t)BH * 96 * NN];
__device__ __nv_bfloat16 g_ph[(size_t)BH * NN * NN];
__device__ __nv_bfloat16 g_pl[(size_t)BH * NN * NN];
__device__ float g_S[(size_t)BH * NN * NN];
__device__ float g_x2[BH * NN];
__device__ float g_pool[BH];
__device__ float g_xw[NHH * NN];
__device__ float g_xp[NHH * NN];
__device__ float g_table[NHH * 63 * 63];
__device__ float g_opre[(size_t)ROWS * CC];

// ---- mma.sync wrapper: D += A * B (bf16 in, f32 acc) ----
__device__ __forceinline__ void mma16816(float* c, uint32_t a0, uint32_t a1,
                                         uint32_t a2, uint32_t a3,
                                         uint32_t b0, uint32_t b1) {
    asm volatile(
        "mma.sync.aligned.m16n8k16.row.col.f32.bf16.bf16.f32 "
        "{%0,%1,%2,%3}, {%4,%5,%6,%7}, {%8,%9}, {%0,%1,%2,%3};"
        : "+f"(c[0]), "+f"(c[1]), "+f"(c[2]), "+f"(c[3])
        : "r"(a0), "r"(a1), "r"(a2), "r"(a3), "r"(b0), "r"(b1));
}

__device__ __forceinline__ void split_bf(float v, __nv_bfloat16& hi, __nv_bfloat16& lo) {
    hi = __float2bfloat16(v);
    lo = __float2bfloat16(v - __bfloat162float(hi));
}

// Copy rows x (cols8*8) bf16 tile global -> smem (stride sstride elems)
__device__ __forceinline__ void load_sm(const __nv_bfloat16* __restrict__ g,
                                        size_t gstride, int rows, int cols8,
                                        __nv_bfloat16* s, int sstride, int tid) {
    int total = rows * cols8;
    for (int i = tid; i < total; i += 256) {
        int r = i / cols8, cc = (i - r * cols8) * 8;
        *(uint4*)&s[r * sstride + cc] = *(const uint4*)&g[(size_t)r * gstride + cc];
    }
}

// ---------------------------------------------------------------------------
// K0: zero the k-dim padding (cols 84..95) of q/k hi/lo
// ---------------------------------------------------------------------------
__global__ void k_padzero() {
    int t = blockIdx.x * 256 + threadIdx.x;
    if (t < BH * NN) {
        size_t u = (size_t)t * 48 + 42;  // u32 index of col 84
        uint32_t* qh = (uint32_t*)g_qh;
        uint32_t* ql = (uint32_t*)g_ql;
        uint32_t* kh = (uint32_t*)g_kh;
        uint32_t* kl = (uint32_t*)g_kl;
#pragma unroll
        for (int i = 0; i < 6; i++) {
            qh[u + i] = 0u; ql[u + i] = 0u; kh[u + i] = 0u; kl[u + i] = 0u;
        }
    }
}

// ---------------------------------------------------------------------------
// K1: qkv = x @ W_qkv + b_qkv -> bf16 hi/lo in MMA-friendly layouts
// ---------------------------------------------------------------------------
__global__ void k_qkv(const float* __restrict__ x, const float* __restrict__ Wq,
                      const float* __restrict__ bq) {
    __shared__ float xs[32][33];
    __shared__ float ws[32][96];
    __shared__ float bs[96];
    int t = threadIdx.x;
    int row0 = blockIdx.x * 32;
    for (int i = t; i < 32 * 96; i += 256) ws[i / 96][i % 96] = Wq[i];
    if (t < 96) bs[t] = bq[t];
    for (int i = t; i < 32 * 32; i += 256)
        xs[i >> 5][i & 31] = x[(size_t)row0 * 32 + i];
    __syncthreads();
    for (int idx = t; idx < 32 * 96; idx += 256) {
        int r = idx / 96, j = idx % 96;
        float acc = bs[j];
#pragma unroll
        for (int kk = 0; kk < 32; kk++) acc += xs[r][kk] * ws[kk][j];
        int R = row0 + r;
        int b_ = R / 21, m = R % 21;
        int b = b_ >> 10, n = b_ & 1023;
        int which = j >> 5;
        int hc = j & 31;
        int hh = hc >> 2, c = hc & 3;
        int bh = (b << 3) | hh;
        __nv_bfloat16 hi, lo;
        if (which == 0) {
            split_bf(acc * 0.03125f, hi, lo);  // q pre-scaled by N^-0.5
            size_t di = ((size_t)((bh << 10) | n)) * 96 + (m << 2) + c;
            g_qh[di] = hi; g_ql[di] = lo;
        } else if (which == 1) {
            split_bf(acc, hi, lo);
            size_t di = ((size_t)((bh << 10) | n)) * 96 + (m << 2) + c;
            g_kh[di] = hi; g_kl[di] = lo;
        } else {
            split_bf(acc, hi, lo);
            size_t vi = ((size_t)bh * 96 + (m << 2) + c) * 1024 + n;  // transposed
            g_vth[vi] = hi; g_vtl[vi] = lo;
        }
    }
}

// ---------------------------------------------------------------------------
// K2..K5: LSPE bias chain (unchanged)
// ---------------------------------------------------------------------------
__global__ void k_x2(const float* __restrict__ x, const float* __restrict__ Wsq,
                     const float* __restrict__ bsq) {
    __shared__ float w[DD];
    int t = threadIdx.x;
    if (t < DD) w[t] = Wsq[t];
    __syncthreads();
    int gid = blockIdx.x * blockDim.x + t;
    if (gid >= BH * NN) return;
    int n = gid & 1023;
    int bh = gid >> 10;
    int h = bh & 7, b = bh >> 3;
    const float* xr = x + (size_t)(b * NN + n) * (MM * CC) + h * 4;
    float acc = bsq[0];
#pragma unroll
    for (int m = 0; m < MM; m++)
#pragma unroll
        for (int c = 0; c < 4; c++) acc += xr[m * 32 + c] * w[m * 4 + c];
    g_x2[gid] = acc;
}

__global__ void k_pool() {
    int bh = blockIdx.x;
    int t = threadIdx.x;
    const float* p = g_x2 + (size_t)bh * NN;
    float s = 0.f, mx = -1e30f;
    for (int i = t; i < NN; i += 256) { float v = p[i]; s += v; mx = fmaxf(mx, v); }
    __shared__ float ss[256], smx[256];
    ss[t] = s; smx[t] = mx;
    __syncthreads();
    for (int o = 128; o > 0; o >>= 1) {
        if (t < o) { ss[t] += ss[t + o]; smx[t] = fmaxf(smx[t], smx[t + o]); }
        __syncthreads();
    }
    if (t == 0) g_pool[bh] = ss[0] * (1.0f / 1024.0f) + smx[0];
}

__global__ void k_spatial(const float* __restrict__ Wdw, const float* __restrict__ bdw) {
    int sb = blockIdx.x >> 3, h = blockIdx.x & 7;
    int o = sb * 8 + h, ic = o >> 1;
    __shared__ float xs[NN];
    __shared__ float wk[9];
    int t = threadIdx.x;
    if (t < 9) wk[t] = Wdw[o * 9 + t];
    float acc[4] = {0.f, 0.f, 0.f, 0.f};
    float scal = 0.f;
    for (int b = 0; b < 4; b++) {
        __syncthreads();
        for (int i = t; i < NN; i += 256) xs[i] = g_x2[(size_t)(b * 8 + ic) * NN + i];
        __syncthreads();
        scal += g_pool[b * 8 + h];
#pragma unroll
        for (int qq = 0; qq < 4; qq++) {
            int pix = qq * 256 + t;
            int y = pix >> 5, xx = pix & 31;
            float s = 0.f;
#pragma unroll
            for (int dy = -1; dy <= 1; dy++)
#pragma unroll
                for (int dx = -1; dx <= 1; dx++) {
                    int yy = y + dy, xq = xx + dx;
                    if (yy >= 0 && yy < 32 && xq >= 0 && xq < 32)
                        s += xs[yy * 32 + xq] * wk[(dy + 1) * 3 + (dx + 1)];
                }
            acc[qq] += s;
        }
    }
    float bo = bdw[o];
    float* dst = sb ? g_xp : g_xw;
#pragma unroll
    for (int qq = 0; qq < 4; qq++) {
        int pix = qq * 256 + t;
        dst[h * NN + pix] = acc[qq] * 0.25f + bo + scal * 0.25f;
    }
}

__global__ void k_table() {
    int h = blockIdx.x;
    __shared__ float xp[NN], xw[NN];
    int t = threadIdx.x;
    for (int i = t; i < NN; i += 256) { xp[i] = g_xp[h * NN + i]; xw[i] = g_xw[h * NN + i]; }
    __syncthreads();
    for (int idx = t; idx < 63 * 63; idx += 256) {
        int i = idx / 63, j = idx % 63;
        int a0 = max(0, i - 31), a1 = min(31, i);
        int b0 = max(0, j - 31), b1 = min(31, j);
        float acc = 0.f;
        for (int a = a0; a <= a1; a++)
            for (int bb = b0; bb <= b1; bb++)
                acc += xp[(i - a) * 32 + (j - bb)] * xw[a * 32 + bb];
        g_table[h * 3969 + idx] = acc;
    }
}

// ---------------------------------------------------------------------------
// K6: S = Q@K^T (mma.sync bf16 split) + bias -> g_S fp32
//     CTA: 128x128 tile, 8 warps (4M x 2N), warp 32x64
// ---------------------------------------------------------------------------
#define QK_STRIDE 104
#define QK_TILE   (128 * QK_STRIDE)           // elems per operand tile
#define QK_SMEM   ((4 * QK_TILE) * 2 + 441 * 4)

__global__ void __launch_bounds__(256, 1) k_qk_mma() {
    extern __shared__ __nv_bfloat16 sm[];
    __nv_bfloat16* Qh = sm;
    __nv_bfloat16* Ql = sm + QK_TILE;
    __nv_bfloat16* Kh = sm + 2 * QK_TILE;
    __nv_bfloat16* Kl = sm + 3 * QK_TILE;
    float* tabs = (float*)(sm + 4 * QK_TILE);

    const int tid = threadIdx.x, wid = tid >> 5, lane = tid & 31;
    const int g = lane >> 2, tq = lane & 3;
    const int It = blockIdx.x, bh = blockIdx.y, h = bh & 7;
    const int rt = It * 128;
    const int m0w = (wid >> 1) * 32, n0w = (wid & 1) * 64;

    load_sm(g_qh + ((size_t)(bh << 10) + rt) * 96, 96, 128, 12, Qh, QK_STRIDE, tid);
    load_sm(g_ql + ((size_t)(bh << 10) + rt) * 96, 96, 128, 12, Ql, QK_STRIDE, tid);

    for (int Jt = 0; Jt < 8; Jt++) {
        int ct = Jt * 128;
        __syncthreads();
        load_sm(g_kh + ((size_t)(bh << 10) + ct) * 96, 96, 128, 12, Kh, QK_STRIDE, tid);
        load_sm(g_kl + ((size_t)(bh << 10) + ct) * 96, 96, 128, 12, Kl, QK_STRIDE, tid);
        {
            const float* tg = g_table + h * 3969 + (4 * (It - Jt) + 28) * 63;
            for (int i = tid; i < 441; i += 256) tabs[i] = tg[i];
        }
        __syncthreads();

        float acc[2][8][4];
#pragma unroll
        for (int mt = 0; mt < 2; mt++)
#pragma unroll
            for (int j = 0; j < 8; j++)
#pragma unroll
                for (int q = 0; q < 4; q++) acc[mt][j][q] = 0.f;

#pragma unroll
        for (int ks = 0; ks < 6; ks++) {
            int k0 = ks * 16;
            uint32_t ah[2][4], al[2][4];
#pragma unroll
            for (int mt = 0; mt < 2; mt++) {
                int r = m0w + mt * 16 + g;
                const uint32_t* p0h = (const uint32_t*)&Qh[r * QK_STRIDE + k0];
                const uint32_t* p1h = (const uint32_t*)&Qh[(r + 8) * QK_STRIDE + k0];
                const uint32_t* p0l = (const uint32_t*)&Ql[r * QK_STRIDE + k0];
                const uint32_t* p1l = (const uint32_t*)&Ql[(r + 8) * QK_STRIDE + k0];
                ah[mt][0] = p0h[tq]; ah[mt][1] = p1h[tq];
                ah[mt][2] = p0h[tq + 4]; ah[mt][3] = p1h[tq + 4];
                al[mt][0] = p0l[tq]; al[mt][1] = p1l[tq];
                al[mt][2] = p0l[tq + 4]; al[mt][3] = p1l[tq + 4];
            }
#pragma unroll
            for (int j = 0; j < 8; j++) {
                int nr = n0w + j * 8 + g;
                const uint32_t* pbh = (const uint32_t*)&Kh[nr * QK_STRIDE + k0];
                const uint32_t* pbl = (const uint32_t*)&Kl[nr * QK_STRIDE + k0];
                uint32_t bh0 = pbh[tq], bh1 = pbh[tq + 4];
                uint32_t bl0 = pbl[tq], bl1 = pbl[tq + 4];
#pragma unroll
                for (int mt = 0; mt < 2; mt++) {
                    mma16816(acc[mt][j], ah[mt][0], ah[mt][1], ah[mt][2], ah[mt][3], bh0, bh1);
                    mma16816(acc[mt][j], al[mt][0], al[mt][1], al[mt][2], al[mt][3], bh0, bh1);
                    mma16816(acc[mt][j], ah[mt][0], ah[mt][1], ah[mt][2], ah[mt][3], bl0, bl1);
                }
            }
        }

        // epilogue: bias add + store fp32 S
        float* Sp = g_S + (size_t)bh * (1024 * 1024) + (size_t)rt * 1024 + ct;
#pragma unroll
        for (int mt = 0; mt < 2; mt++) {
#pragma unroll
            for (int j = 0; j < 8; j++) {
                int jl = n0w + j * 8 + 2 * tq;
#pragma unroll
                for (int half = 0; half < 2; half++) {
                    int il = m0w + mt * 16 + g + half * 8;
                    int dRow = (il >> 5) - (jl >> 5) + 3;
                    int dCol = (il & 31) - (jl & 31) + 31;
                    float b0 = tabs[dRow * 63 + dCol];
                    float b1 = tabs[dRow * 63 + dCol - 1];
                    float2 v;
                    v.x = acc[mt][j][half * 2 + 0] + b0;
                    v.y = acc[mt][j][half * 2 + 1] + b1;
                    *(float2*)&Sp[(size_t)il * 1024 + jl] = v;
                }
            }
        }
    }
}

// ---------------------------------------------------------------------------
// K7: row softmax over S, writes P as bf16 hi/lo
// ---------------------------------------------------------------------------
__global__ void k_softmax() {
    int t = threadIdx.x;
    const float* p = g_S + (size_t)blockIdx.x * NN;
    float4 v = ((const float4*)p)[t];
    __shared__ float red[8];
    __shared__ float red2[8];
    float mx = fmaxf(fmaxf(v.x, v.y), fmaxf(v.z, v.w));
#pragma unroll
    for (int o = 16; o; o >>= 1) mx = fmaxf(mx, __shfl_xor_sync(0xffffffffu, mx, o));
    if ((t & 31) == 0) red[t >> 5] = mx;
    __syncthreads();
    if (t < 32) {
        float m = (t < 8) ? red[t] : -1e30f;
#pragma unroll
        for (int o = 4; o; o >>= 1) m = fmaxf(m, __shfl_xor_sync(0xffffffffu, m, o));
        if (t == 0) red[0] = m;
    }
    __syncthreads();
    float M = red[0];
    v.x = __expf(v.x - M); v.y = __expf(v.y - M);
    v.z = __expf(v.z - M); v.w = __expf(v.w - M);
    float s = v.x + v.y + v.z + v.w;
#pragma unroll
    for (int o = 16; o; o >>= 1) s += __shfl_xor_sync(0xffffffffu, s, o);
    if ((t & 31) == 0) red2[t >> 5] = s;
    __syncthreads();
    if (t < 32) {
        float m2 = (t < 8) ? red2[t] : 0.f;
#pragma unroll
        for (int o = 4; o; o >>= 1) m2 += __shfl_xor_sync(0xffffffffu, m2, o);
        if (t == 0) red2[0] = m2;
    }
    __syncthreads();
    float inv = 1.0f / red2[0];
    v.x *= inv; v.y *= inv; v.z *= inv; v.w *= inv;
    __nv_bfloat162 h01, h23, l01, l23;
    h01.x = __float2bfloat16(v.x); h01.y = __float2bfloat16(v.y);
    h23.x = __float2bfloat16(v.z); h23.y = __float2bfloat16(v.w);
    l01.x = __float2bfloat16(v.x - __bfloat162float(h01.x));
    l01.y = __float2bfloat16(v.y - __bfloat162float(h01.y));
    l23.x = __float2bfloat16(v.z - __bfloat162float(h23.x));
    l23.y = __float2bfloat16(v.w - __bfloat162float(h23.y));
    size_t base = (size_t)blockIdx.x * NN + t * 4;
    ((__nv_bfloat162*)(g_ph + base))[0] = h01;
    ((__nv_bfloat162*)(g_ph + base))[1] = h23;
    ((__nv_bfloat162*)(g_pl + base))[0] = l01;
    ((__nv_bfloat162*)(g_pl + base))[1] = l23;
}

// ---------------------------------------------------------------------------
// K8: O = P @ V^T-layout (mma.sync bf16 split), CTA 128 rows x 96 d
//     8 warps (4M x 2N), warp 32x48; K loop: 8 chunks of 128
// ---------------------------------------------------------------------------
#define PV_STRIDE 136
#define PV_PTILE  (128 * PV_STRIDE)
#define PV_VTILE  (96 * PV_STRIDE)
#define PV_SMEM   ((2 * PV_PTILE + 2 * PV_VTILE) * 2)

__global__ void __launch_bounds__(256, 1) k_pv_mma() {
    extern __shared__ __nv_bfloat16 sm[];
    __nv_bfloat16* Ph = sm;
    __nv_bfloat16* Pl = sm + PV_PTILE;
    __nv_bfloat16* Vh = sm + 2 * PV_PTILE;
    __nv_bfloat16* Vl = sm + 2 * PV_PTILE + PV_VTILE;

    const int tid = threadIdx.x, wid = tid >> 5, lane = tid & 31;
    const int g = lane >> 2, tq = lane & 3;
    const int It = blockIdx.x, bh = blockIdx.y;
    const int rt = It * 128;
    const int m0w = (wid >> 1) * 32, n0w = (wid & 1) * 48;

    float acc[2][6][4];
#pragma unroll
    for (int mt = 0; mt < 2; mt++)
#pragma unroll
        for (int j = 0; j < 6; j++)
#pragma unroll
            for (int q = 0; q < 4; q++) acc[mt][j][q] = 0.f;

    for (int nb = 0; nb < 8; nb++) {
        __syncthreads();
        load_sm(g_ph + ((size_t)(bh << 10) + rt) * 1024 + nb * 128, 1024, 128, 16, Ph, PV_STRIDE, tid);
        load_sm(g_pl + ((size_t)(bh << 10) + rt) * 1024 + nb * 128, 1024, 128, 16, Pl, PV_STRIDE, tid);
        load_sm(g_vth + (size_t)bh * (96 * 1024) + nb * 128, 1024, 96, 16, Vh, PV_STRIDE, tid);
        load_sm(g_vtl + (size_t)bh * (96 * 1024) + nb * 128, 1024, 96, 16, Vl, PV_STRIDE, tid);
        __syncthreads();

#pragma unroll
        for (int ks = 0; ks < 8; ks++) {
            int k0 = ks * 16;
            uint32_t ah[2][4], al[2][4];
#pragma unroll
            for (int mt = 0; mt < 2; mt++) {
                int r = m0w + mt * 16 + g;
                const uint32_t* p0h = (const uint32_t*)&Ph[r * PV_STRIDE + k0];
                const uint32_t* p1h = (const uint32_t*)&Ph[(r + 8) * PV_STRIDE + k0];
                const uint32_t* p0l = (const uint32_t*)&Pl[r * PV_STRIDE + k0];
                const uint32_t* p1l = (const uint32_t*)&Pl[(r + 8) * PV_STRIDE + k0];
                ah[mt][0] = p0h[tq]; ah[mt][1] = p1h[tq];
                ah[mt][2] = p0h[tq + 4]; ah[mt][3] = p1h[tq + 4];
                al[mt][0] = p0l[tq]; al[mt][1] = p1l[tq];
                al[mt][2] = p0l[tq + 4]; al[mt][3] = p1l[tq + 4];
            }
#pragma unroll
            for (int j = 0; j < 6; j++) {
                int nr = n0w + j * 8 + g;  // d index
                const uint32_t* pbh = (const uint32_t*)&Vh[nr * PV_STRIDE + k0];
                const uint32_t* pbl = (const uint32_t*)&Vl[nr * PV_STRIDE + k0];
                uint32_t bh0 = pbh[tq], bh1 = pbh[tq + 4];
                uint32_t bl0 = pbl[tq], bl1 = pbl[tq + 4];
#pragma unroll
                for (int mt = 0; mt < 2; mt++) {
                    mma16816(acc[mt][j], ah[mt][0], ah[mt][1], ah[mt][2], ah[mt][3], bh0, bh1);
                    mma16816(acc[mt][j], al[mt][0], al[mt][1], al[mt][2], al[mt][3], bh0, bh1);
                    mma16816(acc[mt][j], ah[mt][0], ah[mt][1], ah[mt][2], ah[mt][3], bl0, bl1);
                }
            }
        }
    }

    // scatter: O[row, d] -> g_opre[((b<<10)+row)*21 + m][h*4+c]
    int b = bh >> 3, hh = bh & 7;
#pragma unroll
    for (int mt = 0; mt < 2; mt++) {
#pragma unroll
        for (int j = 0; j < 6; j++) {
            int d0 = n0w + j * 8 + 2 * tq;
#pragma unroll
            for (int half = 0; half < 2; half++) {
                int row = rt + m0w + mt * 16 + g + half * 8;
#pragma unroll
                for (int e = 0; e < 2; e++) {
                    int d = d0 + e;
                    if (d < DD) {
                        int m = d >> 2, c = d & 3;
                        g_opre[((size_t)((b << 10) + row) * 21 + m) * 32 + (hh << 2) + c] =
                            acc[mt][j][half * 2 + e];
                    }
                }
            }
        }
    }
}

// ---------------------------------------------------------------------------
// K9: out = opre @ W_proj + b_proj
// ---------------------------------------------------------------------------
__global__ void k_proj(const float* __restrict__ Wp, const float* __restrict__ bp,
                       float* __restrict__ out) {
    __shared__ float xs[32][33];
    __shared__ float ws[32][32];
    __shared__ float bs[32];
    int t = threadIdx.x;
    int row0 = blockIdx.x * 32;
    for (int i = t; i < 1024; i += 256) ws[i >> 5][i & 31] = Wp[i];
    if (t < 32) bs[t] = bp[t];
    for (int i = t; i < 1024; i += 256) xs[i >> 5][i & 31] = g_opre[(size_t)row0 * 32 + i];
    __syncthreads();
    for (int idx = t; idx < 1024; idx += 256) {
        int r = idx >> 5, j = idx & 31;
        float acc = bs[j];
#pragma unroll
        for (int kk = 0; kk < 32; kk++) acc += xs[r][kk] * ws[kk][j];
        out[(size_t)(row0 + r) * 32 + j] = acc;
    }
}

// ---------------------------------------------------------------------------
extern "C" void kernel_launch(void* const* d_in, const int* in_sizes, int n_in,
                              void* d_out, int out_size) {
    (void)in_sizes; (void)n_in; (void)out_size;
    const float* x   = (const float*)d_in[0];
    const float* Wq  = (const float*)d_in[1];
    const float* bq  = (const float*)d_in[2];
    const float* Wp  = (const float*)d_in[3];
    const float* bp  = (const float*)d_in[4];
    const float* Wsq = (const float*)d_in[5];
    const float* bsq = (const float*)d_in[6];
    const float* Wdw = (const float*)d_in[7];
    const float* bdw = (const float*)d_in[8];
    float* out = (float*)d_out;

    static int init_done = 0;
    if (!init_done) {
        cudaFuncSetAttribute(k_qk_mma, cudaFuncAttributeMaxDynamicSharedMemorySize, QK_SMEM);
        cudaFuncSetAttribute(k_pv_mma, cudaFuncAttributeMaxDynamicSharedMemorySize, PV_SMEM);
        init_done = 1;
    }

    k_padzero<<<128, 256>>>();
    k_qkv<<<ROWS / 32, 256>>>(x, Wq, bq);
    k_x2<<<(BH * NN) / 256, 256>>>(x, Wsq, bsq);
    k_pool<<<BH, 256>>>();
    k_spatial<<<16, 256>>>(Wdw, bdw);
    k_table<<<NHH, 256>>>();
    k_qk_mma<<<dim3(8, BH), 256, QK_SMEM>>>();
    k_softmax<<<BH * NN, 256>>>();
    k_pv_mma<<<dim3(8, BH), 256, PV_SMEM>>>();
    k_proj<<<ROWS / 32, 256>>>(Wp, bp, out);
}

// round 5
// speedup vs baseline: 2.2977x; 2.0052x over previous
#include <cuda_runtime.h>
#include <cuda_fp16.h>
#include <math.h>
#include <stdint.h>

#define NHH  8
#define NN   1024
#define MM   21
#define CC   32
#define DD   84
#define BH   32
#define ROWS 86016

// ---- scratch (device globals) ----
__device__ __half g_q[(size_t)BH * NN * 96];    // [bh][n][d], q pre-scaled by 1/32
__device__ __half g_k[(size_t)BH * NN * 96];    // [bh][n][d]
__device__ __half g_vt[(size_t)BH * 96 * NN];   // [bh][d][n]
__device__ float g_x2[BH * NN];
__device__ float g_pool[BH];
__device__ float g_xw[NHH * NN];
__device__ float g_xp[NHH * NN];
__device__ float g_table[NHH * 63 * 63];
__device__ float g_opre[(size_t)ROWS * CC];

// ---- fp16 mma.sync: D(f32) += A(f16) * B(f16) ----
__device__ __forceinline__ void mma16816(float* c, uint32_t a0, uint32_t a1,
                                         uint32_t a2, uint32_t a3,
                                         uint32_t b0, uint32_t b1) {
    asm volatile(
        "mma.sync.aligned.m16n8k16.row.col.f32.f16.f16.f32 "
        "{%0,%1,%2,%3}, {%4,%5,%6,%7}, {%8,%9}, {%0,%1,%2,%3};"
        : "+f"(c[0]), "+f"(c[1]), "+f"(c[2]), "+f"(c[3])
        : "r"(a0), "r"(a1), "r"(a2), "r"(a3), "r"(b0), "r"(b1));
}

// copy rows x (cols8*8) half tile gmem -> smem
__device__ __forceinline__ void load_sm(const __half* __restrict__ g, size_t gstride,
                                        int rows, int cols8, __half* s, int sstride,
                                        int tid) {
    int total = rows * cols8;
    for (int i = tid; i < total; i += 256) {
        int r = i / cols8, cc = (i - r * cols8) * 8;
        *(uint4*)&s[r * sstride + cc] = *(const uint4*)&g[(size_t)r * gstride + cc];
    }
}

// ---------------------------------------------------------------------------
// K1: qkv = x @ W_qkv + b_qkv -> fp16 q (scaled), k, v^T
// ---------------------------------------------------------------------------
__global__ void k_qkv(const float* __restrict__ x, const float* __restrict__ Wq,
                      const float* __restrict__ bq) {
    __shared__ float xs[32][33];
    __shared__ float ws[32][96];
    __shared__ float bs[96];
    int t = threadIdx.x;
    int row0 = blockIdx.x * 32;
    for (int i = t; i < 32 * 96; i += 256) ws[i / 96][i % 96] = Wq[i];
    if (t < 96) bs[t] = bq[t];
    for (int i = t; i < 32 * 32; i += 256)
        xs[i >> 5][i & 31] = x[(size_t)row0 * 32 + i];
    __syncthreads();
    for (int idx = t; idx < 32 * 24; idx += 256) {
        int r = idx / 24, jg = idx % 24;
        int j0 = jg * 4;
        float a0 = bs[j0], a1 = bs[j0 + 1], a2 = bs[j0 + 2], a3 = bs[j0 + 3];
#pragma unroll
        for (int kk = 0; kk < 32; kk++) {
            float xv = xs[r][kk];
            a0 += xv * ws[kk][j0];
            a1 += xv * ws[kk][j0 + 1];
            a2 += xv * ws[kk][j0 + 2];
            a3 += xv * ws[kk][j0 + 3];
        }
        int R = row0 + r;
        int b_ = R / 21, m = R % 21;
        int b = b_ >> 10, n = b_ & 1023;
        int which = j0 >> 5;
        int hc = j0 & 31;
        int hh = hc >> 2;
        int bh = (b << 3) | hh;
        if (which == 0) {
            const float sc = 0.03125f;
            __half2 p01 = __float22half2_rn(make_float2(a0 * sc, a1 * sc));
            __half2 p23 = __float22half2_rn(make_float2(a2 * sc, a3 * sc));
            size_t di = ((size_t)((bh << 10) | n)) * 96 + (m << 2);
            uint2 pk;
            pk.x = *(uint32_t*)&p01; pk.y = *(uint32_t*)&p23;
            *(uint2*)&g_q[di] = pk;
        } else if (which == 1) {
            __half2 p01 = __float22half2_rn(make_float2(a0, a1));
            __half2 p23 = __float22half2_rn(make_float2(a2, a3));
            size_t di = ((size_t)((bh << 10) | n)) * 96 + (m << 2);
            uint2 pk;
            pk.x = *(uint32_t*)&p01; pk.y = *(uint32_t*)&p23;
            *(uint2*)&g_k[di] = pk;
        } else {
            size_t vi = ((size_t)bh * 96 + (m << 2)) * 1024 + n;
            g_vt[vi]            = __float2half_rn(a0);
            g_vt[vi + 1024]     = __float2half_rn(a1);
            g_vt[vi + 2048]     = __float2half_rn(a2);
            g_vt[vi + 3072]     = __float2half_rn(a3);
        }
    }
}

// ---------------------------------------------------------------------------
// K2..K5: LSPE bias chain
// ---------------------------------------------------------------------------
__global__ void k_x2(const float* __restrict__ x, const float* __restrict__ Wsq,
                     const float* __restrict__ bsq) {
    __shared__ float w[DD];
    int t = threadIdx.x;
    if (t < DD) w[t] = Wsq[t];
    __syncthreads();
    int gid = blockIdx.x * blockDim.x + t;
    if (gid >= BH * NN) return;
    int n = gid & 1023;
    int bh = gid >> 10;
    int h = bh & 7, b = bh >> 3;
    const float* xr = x + (size_t)(b * NN + n) * (MM * CC) + h * 4;
    float acc = bsq[0];
#pragma unroll
    for (int m = 0; m < MM; m++)
#pragma unroll
        for (int c = 0; c < 4; c++) acc += xr[m * 32 + c] * w[m * 4 + c];
    g_x2[gid] = acc;
}

__global__ void k_pool() {
    int bh = blockIdx.x;
    int t = threadIdx.x;
    const float* p = g_x2 + (size_t)bh * NN;
    float s = 0.f, mx = -1e30f;
    for (int i = t; i < NN; i += 256) { float v = p[i]; s += v; mx = fmaxf(mx, v); }
    __shared__ float ss[256], smx[256];
    ss[t] = s; smx[t] = mx;
    __syncthreads();
    for (int o = 128; o > 0; o >>= 1) {
        if (t < o) { ss[t] += ss[t + o]; smx[t] = fmaxf(smx[t], smx[t + o]); }
        __syncthreads();
    }
    if (t == 0) g_pool[bh] = ss[0] * (1.0f / 1024.0f) + smx[0];
}

__global__ void k_spatial(const float* __restrict__ Wdw, const float* __restrict__ bdw) {
    int sb = blockIdx.x >> 3, h = blockIdx.x & 7;
    int o = sb * 8 + h, ic = o >> 1;
    __shared__ float xs[NN];
    __shared__ float wk[9];
    int t = threadIdx.x;
    if (t < 9) wk[t] = Wdw[o * 9 + t];
    float acc[4] = {0.f, 0.f, 0.f, 0.f};
    float scal = 0.f;
    for (int b = 0; b < 4; b++) {
        __syncthreads();
        for (int i = t; i < NN; i += 256) xs[i] = g_x2[(size_t)(b * 8 + ic) * NN + i];
        __syncthreads();
        scal += g_pool[b * 8 + h];
#pragma unroll
        for (int qq = 0; qq < 4; qq++) {
            int pix = qq * 256 + t;
            int y = pix >> 5, xx = pix & 31;
            float s = 0.f;
#pragma unroll
            for (int dy = -1; dy <= 1; dy++)
#pragma unroll
                for (int dx = -1; dx <= 1; dx++) {
                    int yy = y + dy, xq = xx + dx;
                    if (yy >= 0 && yy < 32 && xq >= 0 && xq < 32)
                        s += xs[yy * 32 + xq] * wk[(dy + 1) * 3 + (dx + 1)];
                }
            acc[qq] += s;
        }
    }
    float bo = bdw[o];
    float* dst = sb ? g_xp : g_xw;
#pragma unroll
    for (int qq = 0; qq < 4; qq++) {
        int pix = qq * 256 + t;
        dst[h * NN + pix] = acc[qq] * 0.25f + bo + scal * 0.25f;
    }
}

__global__ void k_table() {
    int h = blockIdx.x;
    __shared__ float xp[NN], xw[NN];
    int t = threadIdx.x;
    for (int i = t; i < NN; i += 256) { xp[i] = g_xp[h * NN + i]; xw[i] = g_xw[h * NN + i]; }
    __syncthreads();
    for (int idx = t; idx < 63 * 63; idx += 256) {
        int i = idx / 63, j = idx % 63;
        int a0 = max(0, i - 31), a1 = min(31, i);
        int b0 = max(0, j - 31), b1 = min(31, j);
        float acc = 0.f;
        for (int a = a0; a <= a1; a++)
            for (int bb = b0; bb <= b1; bb++)
                acc += xp[(i - a) * 32 + (j - bb)] * xw[a * 32 + bb];
        g_table[h * 3969 + idx] = acc;
    }
}

// ---------------------------------------------------------------------------
// K6: fused flash attention.  CTA = 128 q-rows; 8 warps x 16 rows.
//     Loop 8 kv-blocks of 128: S=QK^T(+bias) -> online softmax -> O += P V.
// ---------------------------------------------------------------------------
#define QSTR 104
#define VSTR 136
#define FL_Q    0
#define FL_K    (128 * QSTR)
#define FL_V    (2 * 128 * QSTR)
#define FL_TAB  (2 * 128 * QSTR + 96 * VSTR)          // in halves
#define FL_SMEM (FL_TAB * 2 + 441 * 4)

__global__ void __launch_bounds__(256, 1) k_flash() {
    extern __shared__ __half sm[];
    __half* Qs = sm + FL_Q;
    __half* Ks = sm + FL_K;
    __half* Vs = sm + FL_V;
    float* tabs = (float*)(sm + FL_TAB);

    const int tid = threadIdx.x, w = tid >> 5, lane = tid & 31;
    const int g = lane >> 2, tq = lane & 3;
    const int It = blockIdx.x, bh = blockIdx.y, h = bh & 7;
    const int rt = It * 128;
    const int ri5 = w >> 1;                   // (local row)>>5
    const int ra0 = (w & 1) * 16 + g;         // (local row)&31 for half 0

    load_sm(g_q + ((size_t)(bh << 10) + rt) * 96, 96, 128, 12, Qs, QSTR, tid);

    float m0 = -1e30f, m1 = -1e30f, l0 = 0.f, l1 = 0.f;
    float oacc[12][4];
#pragma unroll
    for (int j = 0; j < 12; j++)
#pragma unroll
        for (int e = 0; e < 4; e++) oacc[j][e] = 0.f;

    for (int nb = 0; nb < 8; nb++) {
        int ct = nb * 128;
        __syncthreads();
        load_sm(g_k + ((size_t)(bh << 10) + ct) * 96, 96, 128, 12, Ks, QSTR, tid);
        load_sm(g_vt + (size_t)bh * (96 * 1024) + ct, 1024, 96, 16, Vs, VSTR, tid);
        {
            const float* tg = g_table + h * 3969 + (4 * (It - nb) + 28) * 63;
            for (int i = tid; i < 441; i += 256) tabs[i] = tg[i];
        }
        __syncthreads();

        // ---- S = Q K^T ----
        float sacc[16][4];
#pragma unroll
        for (int j = 0; j < 16; j++)
#pragma unroll
            for (int e = 0; e < 4; e++) sacc[j][e] = 0.f;

#pragma unroll
        for (int ks = 0; ks < 6; ks++) {
            int k0 = ks * 16;
            int r = w * 16 + g;
            const uint32_t* p0 = (const uint32_t*)&Qs[r * QSTR + k0];
            const uint32_t* p1 = (const uint32_t*)&Qs[(r + 8) * QSTR + k0];
            uint32_t a0 = p0[tq], a1 = p1[tq], a2 = p0[tq + 4], a3 = p1[tq + 4];
#pragma unroll
            for (int j = 0; j < 16; j++) {
                const uint32_t* pb = (const uint32_t*)&Ks[(j * 8 + g) * QSTR + k0];
                mma16816(sacc[j], a0, a1, a2, a3, pb[tq], pb[tq + 4]);
            }
        }

        // ---- bias + row max ----
        float rmax0 = -1e30f, rmax1 = -1e30f;
#pragma unroll
        for (int j = 0; j < 16; j++) {
            int jl = j * 8 + 2 * tq;
            int rj5 = jl >> 5, cj = jl & 31;
            int dR0 = (ri5 - rj5 + 3) * 63;
            float b00 = tabs[dR0 + ra0 - cj + 31];
            float b01 = tabs[dR0 + ra0 - cj + 30];
            float b10 = tabs[dR0 + ra0 + 8 - cj + 31];
            float b11 = tabs[dR0 + ra0 + 8 - cj + 30];
            sacc[j][0] += b00; sacc[j][1] += b01;
            sacc[j][2] += b10; sacc[j][3] += b11;
            rmax0 = fmaxf(rmax0, fmaxf(sacc[j][0], sacc[j][1]));
            rmax1 = fmaxf(rmax1, fmaxf(sacc[j][2], sacc[j][3]));
        }
        rmax0 = fmaxf(rmax0, __shfl_xor_sync(0xffffffffu, rmax0, 1));
        rmax0 = fmaxf(rmax0, __shfl_xor_sync(0xffffffffu, rmax0, 2));
        rmax1 = fmaxf(rmax1, __shfl_xor_sync(0xffffffffu, rmax1, 1));
        rmax1 = fmaxf(rmax1, __shfl_xor_sync(0xffffffffu, rmax1, 2));

        // ---- online rescale ----
        float mn0 = fmaxf(m0, rmax0), mn1 = fmaxf(m1, rmax1);
        float al0 = __expf(m0 - mn0), al1 = __expf(m1 - mn1);
        m0 = mn0; m1 = mn1;
        float ls0 = 0.f, ls1 = 0.f;
#pragma unroll
        for (int j = 0; j < 16; j++) {
            sacc[j][0] = __expf(sacc[j][0] - mn0);
            sacc[j][1] = __expf(sacc[j][1] - mn0);
            sacc[j][2] = __expf(sacc[j][2] - mn1);
            sacc[j][3] = __expf(sacc[j][3] - mn1);
            ls0 += sacc[j][0] + sacc[j][1];
            ls1 += sacc[j][2] + sacc[j][3];
        }
        l0 = l0 * al0 + ls0;
        l1 = l1 * al1 + ls1;
#pragma unroll
        for (int j = 0; j < 12; j++) {
            oacc[j][0] *= al0; oacc[j][1] *= al0;
            oacc[j][2] *= al1; oacc[j][3] *= al1;
        }

        // ---- O += P V ----
#pragma unroll
        for (int kk = 0; kk < 8; kk++) {
            __half2 h0 = __float22half2_rn(make_float2(sacc[2 * kk][0], sacc[2 * kk][1]));
            __half2 h1 = __float22half2_rn(make_float2(sacc[2 * kk][2], sacc[2 * kk][3]));
            __half2 h2 = __float22half2_rn(make_float2(sacc[2 * kk + 1][0], sacc[2 * kk + 1][1]));
            __half2 h3 = __float22half2_rn(make_float2(sacc[2 * kk + 1][2], sacc[2 * kk + 1][3]));
            uint32_t a0 = *(uint32_t*)&h0, a1 = *(uint32_t*)&h1;
            uint32_t a2 = *(uint32_t*)&h2, a3 = *(uint32_t*)&h3;
            int k0 = kk * 16;
#pragma unroll
            for (int j = 0; j < 12; j++) {
                const uint32_t* pb = (const uint32_t*)&Vs[(j * 8 + g) * VSTR + k0];
                mma16816(oacc[j], a0, a1, a2, a3, pb[tq], pb[tq + 4]);
            }
        }
    }

    // ---- epilogue: normalize + scatter to opre (GUARD d < DD!) ----
    l0 += __shfl_xor_sync(0xffffffffu, l0, 1);
    l0 += __shfl_xor_sync(0xffffffffu, l0, 2);
    l1 += __shfl_xor_sync(0xffffffffu, l1, 1);
    l1 += __shfl_xor_sync(0xffffffffu, l1, 2);
    float inv0 = 1.f / l0, inv1 = 1.f / l1;
    int b = bh >> 3;
    int row0 = rt + w * 16 + g, row1 = row0 + 8;
#pragma unroll
    for (int j = 0; j < 12; j++) {
        int d = j * 8 + 2 * tq;
        if (d < DD) {
            int m = d >> 2, c = d & 3;
            size_t o0 = ((size_t)((b << 10) + row0) * 21 + m) * 32 + (h << 2) + c;
            size_t o1 = ((size_t)((b << 10) + row1) * 21 + m) * 32 + (h << 2) + c;
            float2 v0 = make_float2(oacc[j][0] * inv0, oacc[j][1] * inv0);
            float2 v1 = make_float2(oacc[j][2] * inv1, oacc[j][3] * inv1);
            *(float2*)&g_opre[o0] = v0;
            *(float2*)&g_opre[o1] = v1;
        }
    }
}

// ---------------------------------------------------------------------------
// K7: out = opre @ W_proj + b_proj
// ---------------------------------------------------------------------------
__global__ void k_proj(const float* __restrict__ Wp, const float* __restrict__ bp,
                       float* __restrict__ out) {
    __shared__ float xs[32][33];
    __shared__ float ws[32][32];
    __shared__ float bs[32];
    int t = threadIdx.x;
    int row0 = blockIdx.x * 32;
    for (int i = t; i < 1024; i += 256) ws[i >> 5][i & 31] = Wp[i];
    if (t < 32) bs[t] = bp[t];
    for (int i = t; i < 1024; i += 256) xs[i >> 5][i & 31] = g_opre[(size_t)row0 * 32 + i];
    __syncthreads();
    for (int idx = t; idx < 1024; idx += 256) {
        int r = idx >> 5, j = idx & 31;
        float acc = bs[j];
#pragma unroll
        for (int kk = 0; kk < 32; kk++) acc += xs[r][kk] * ws[kk][j];
        out[(size_t)(row0 + r) * 32 + j] = acc;
    }
}

// ---------------------------------------------------------------------------
extern "C" void kernel_launch(void* const* d_in, const int* in_sizes, int n_in,
                              void* d_out, int out_size) {
    (void)in_sizes; (void)n_in; (void)out_size;
    const float* x   = (const float*)d_in[0];
    const float* Wq  = (const float*)d_in[1];
    const float* bq  = (const float*)d_in[2];
    const float* Wp  = (const float*)d_in[3];
    const float* bp  = (const float*)d_in[4];
    const float* Wsq = (const float*)d_in[5];
    const float* bsq = (const float*)d_in[6];
    const float* Wdw = (const float*)d_in[7];
    const float* bdw = (const float*)d_in[8];
    float* out = (float*)d_out;

    static int init_done = 0;
    static void *p_q, *p_k, *p_vt;
    if (!init_done) {
        cudaFuncSetAttribute(k_flash, cudaFuncAttributeMaxDynamicSharedMemorySize, FL_SMEM);
        cudaGetSymbolAddress(&p_q, g_q);
        cudaGetSymbolAddress(&p_k, g_k);
        cudaGetSymbolAddress(&p_vt, g_vt);
        init_done = 1;
    }

    // zero the padding (d = 84..95) of q/k/v^T
    cudaMemsetAsync(p_q, 0, sizeof(g_q));
    cudaMemsetAsync(p_k, 0, sizeof(g_k));
    cudaMemsetAsync(p_vt, 0, sizeof(g_vt));

    k_qkv<<<ROWS / 32, 256>>>(x, Wq, bq);
    k_x2<<<(BH * NN) / 256, 256>>>(x, Wsq, bsq);
    k_pool<<<BH, 256>>>();
    k_spatial<<<16, 256>>>(Wdw, bdw);
    k_table<<<NHH, 256>>>();
    k_flash<<<dim3(8, BH), 256, FL_SMEM>>>();
    k_proj<<<ROWS / 32, 256>>>(Wp, bp, out);
}

// round 7
// speedup vs baseline: 2.8104x; 1.2232x over previous
#include <cuda_runtime.h>
#include <cuda_fp16.h>
#include <math.h>
#include <stdint.h>

#define NHH  8
#define NN   1024
#define MM   21
#define CC   32
#define DD   84
#define BH   32
#define ROWS 86016

// ---- scratch (device globals) ----
__device__ __half g_q[(size_t)BH * NN * 96];    // [bh][n][d], q pre-scaled by 1/32; d>=84 zero
__device__ __half g_k[(size_t)BH * NN * 96];
__device__ __half g_v[(size_t)BH * NN * 96];
__device__ float g_x2[BH * NN];
__device__ float g_pool[BH];
__device__ float g_part[64 * NN];
__device__ float g_table[NHH * 63 * 63];
__device__ float g_opre[(size_t)ROWS * CC];

// ---- fp16 mma.sync: D(f32) += A(f16) * B(f16) ----
__device__ __forceinline__ void mma16816(float* c, uint32_t a0, uint32_t a1,
                                         uint32_t a2, uint32_t a3,
                                         uint32_t b0, uint32_t b1) {
    asm volatile(
        "mma.sync.aligned.m16n8k16.row.col.f32.f16.f16.f32 "
        "{%0,%1,%2,%3}, {%4,%5,%6,%7}, {%8,%9}, {%0,%1,%2,%3};"
        : "+f"(c[0]), "+f"(c[1]), "+f"(c[2]), "+f"(c[3])
        : "r"(a0), "r"(a1), "r"(a2), "r"(a3), "r"(b0), "r"(b1));
}

__device__ __forceinline__ uint32_t smem_u32(const void* p) {
    uint32_t a;
    asm("{ .reg .u64 t; cvta.to.shared.u64 t, %1; cvt.u32.u64 %0, t; }" : "=r"(a) : "l"(p));
    return a;
}
__device__ __forceinline__ void cpa16(uint32_t s, const void* g) {
    asm volatile("cp.async.cg.shared.global [%0], [%1], 16;" :: "r"(s), "l"(g));
}
__device__ __forceinline__ void cpa4(uint32_t s, const void* g) {
    asm volatile("cp.async.ca.shared.global [%0], [%1], 4;" :: "r"(s), "l"(g));
}
#define CP_COMMIT() asm volatile("cp.async.commit_group;" ::: "memory")

// ---------------------------------------------------------------------------
// K1: qkv. One block per (b, n): computes all 21 m x 96 outputs, stages in
//     smem (with zeroed d-padding) and stores coalesced 192B rows.
// ---------------------------------------------------------------------------
__global__ void __launch_bounds__(128) k_qkv(const float* __restrict__ x,
                                             const float* __restrict__ Wq,
                                             const float* __restrict__ bq) {
    __shared__ float xs[21][33];
    __shared__ float ws[32][96];
    __shared__ float bs[96];
    __shared__ __align__(16) __half stage[24 * 96];   // [which*8+hh][96]
    int t = threadIdx.x;
    int b_ = blockIdx.x;
    int b = b_ >> 10, n = b_ & 1023;
    for (int i = t; i < 32 * 96; i += 128) ws[i / 96][i % 96] = Wq[i];
    if (t < 96) bs[t] = bq[t];
    for (int i = t; i < 21 * 32; i += 128) xs[i >> 5][i & 31] = x[(size_t)b_ * (21 * 32) + i];
    // zero d-padding 84..95 of every staged row
    for (int i = t; i < 24 * 12; i += 128) {
        int row = i / 12, e = i - row * 12;
        stage[row * 96 + 84 + e] = __float2half_rn(0.f);
    }
    __syncthreads();
    for (int idx = t; idx < 21 * 96; idx += 128) {
        int m = idx / 96, j = idx - m * 96;
        float acc = bs[j];
#pragma unroll
        for (int kk = 0; kk < 32; kk++) acc += xs[m][kk] * ws[kk][j];
        int which = j >> 5, hc = j & 31, hh = hc >> 2, c = hc & 3;
        float sc = (which == 0) ? 0.03125f : 1.0f;
        stage[(which * 8 + hh) * 96 + (m << 2) + c] = __float2half_rn(acc * sc);
    }
    __syncthreads();
    for (int i = t; i < 24 * 12; i += 128) {
        int row = i / 12, q = i - row * 12;
        int which = row >> 3, hh = row & 7;
        int bh = (b << 3) | hh;
        __half* dst = (which == 0) ? g_q : ((which == 1) ? g_k : g_v);
        *(uint4*)&dst[((size_t)((bh << 10) | n)) * 96 + q * 8] = *(uint4*)&stage[row * 96 + q * 8];
    }
}

// ---------------------------------------------------------------------------
// K2: x2[b,h,n]
// ---------------------------------------------------------------------------
__global__ void k_x2(const float* __restrict__ x, const float* __restrict__ Wsq,
                     const float* __restrict__ bsq) {
    __shared__ float w[DD];
    int t = threadIdx.x;
    if (t < DD) w[t] = Wsq[t];
    __syncthreads();
    int gid = blockIdx.x * blockDim.x + t;
    if (gid >= BH * NN) return;
    int n = gid & 1023;
    int bh = gid >> 10;
    int h = bh & 7, b = bh >> 3;
    const float* xr = x + (size_t)(b * NN + n) * (MM * CC) + h * 4;
    float acc = bsq[0];
#pragma unroll
    for (int m = 0; m < MM; m++)
#pragma unroll
        for (int c = 0; c < 4; c++) acc += xr[m * 32 + c] * w[m * 4 + c];
    g_x2[gid] = acc;
}

// ---------------------------------------------------------------------------
// K3: pooled scalar per (b,h)
// ---------------------------------------------------------------------------
__global__ void k_pool() {
    int bh = blockIdx.x;
    int t = threadIdx.x;
    const float* p = g_x2 + (size_t)bh * NN;
    float s = 0.f, mx = -1e30f;
    for (int i = t; i < NN; i += 256) { float v = p[i]; s += v; mx = fmaxf(mx, v); }
    __shared__ float ss[256], smx[256];
    ss[t] = s; smx[t] = mx;
    __syncthreads();
    for (int o = 128; o > 0; o >>= 1) {
        if (t < o) { ss[t] += ss[t + o]; smx[t] = fmaxf(smx[t], smx[t + o]); }
        __syncthreads();
    }
    if (t == 0) g_pool[bh] = ss[0] * (1.0f / 1024.0f) + smx[0];
}

// ---------------------------------------------------------------------------
// K4: depthwise conv partials: one block per (o, batch) -> g_part
// ---------------------------------------------------------------------------
__global__ void k_spatial_p(const float* __restrict__ Wdw) {
    int o = blockIdx.x >> 2, bb = blockIdx.x & 3, ic = o >> 1;
    __shared__ float xs[NN];
    __shared__ float wk[9];
    int t = threadIdx.x;
    if (t < 9) wk[t] = Wdw[o * 9 + t];
    for (int i = t; i < NN; i += 256) xs[i] = g_x2[(size_t)(bb * 8 + ic) * NN + i];
    __syncthreads();
#pragma unroll
    for (int qq = 0; qq < 4; qq++) {
        int pix = qq * 256 + t;
        int y = pix >> 5, xx = pix & 31;
        float s = 0.f;
#pragma unroll
        for (int dy = -1; dy <= 1; dy++)
#pragma unroll
            for (int dx = -1; dx <= 1; dx++) {
                int yy = y + dy, xq = xx + dx;
                if (yy >= 0 && yy < 32 && xq >= 0 && xq < 32)
                    s += xs[yy * 32 + xq] * wk[(dy + 1) * 3 + (dx + 1)];
            }
        g_part[(size_t)blockIdx.x * NN + pix] = s;
    }
}

// ---------------------------------------------------------------------------
// K5: combine partials + pooled -> x_weight/x_proj, then full correlation
// ---------------------------------------------------------------------------
__global__ void k_table(const float* __restrict__ bdw) {
    int h = blockIdx.x;
    __shared__ float xp[NN], xw[NN];
    int t = threadIdx.x;
    float ps = 0.25f * (g_pool[h] + g_pool[8 + h] + g_pool[16 + h] + g_pool[24 + h]);
    float bw = bdw[h] + ps, bp2 = bdw[8 + h] + ps;
    for (int i = t; i < NN; i += 256) {
        float sw = 0.f, sp = 0.f;
#pragma unroll
        for (int bb = 0; bb < 4; bb++) {
            sw += g_part[(size_t)(h * 4 + bb) * NN + i];
            sp += g_part[(size_t)((8 + h) * 4 + bb) * NN + i];
        }
        xw[i] = 0.25f * sw + bw;
        xp[i] = 0.25f * sp + bp2;
    }
    __syncthreads();
    for (int idx = t; idx < 63 * 63; idx += 256) {
        int i = idx / 63, j = idx % 63;
        int a0 = max(0, i - 31), a1 = min(31, i);
        int b0 = max(0, j - 31), b1 = min(31, j);
        float acc = 0.f;
        for (int a = a0; a <= a1; a++)
            for (int bb = b0; bb <= b1; bb++)
                acc += xp[(i - a) * 32 + (j - bb)] * xw[a * 32 + bb];
        g_table[h * 3969 + idx] = acc;
    }
}

// ---------------------------------------------------------------------------
// K6: fused flash attention with cp.async double buffering.
//     smem bytes: Q[0,26624) K0 K1 V0 V1 (26624 each) tab0 tab1 (1776 each)
// ---------------------------------------------------------------------------
#define FL_KOFF(s) (26624 + (s) * 26624)
#define FL_VOFF(s) (79872 + (s) * 26624)
#define FL_TOFF(s) (133120 + (s) * 1776)
#define FL_SMEM    136672

__device__ __forceinline__ void cpa_tile(uint32_t dstb, const __half* __restrict__ g, int tid) {
    for (int i = tid; i < 1536; i += 256) {
        int r = i / 12, q = i - r * 12;
        cpa16(dstb + r * 208 + q * 16, g + r * 96 + q * 8);
    }
}

__global__ void __launch_bounds__(256, 1) k_flash() {
    extern __shared__ char smem[];
    uint32_t sb = smem_u32(smem);
    const int tid = threadIdx.x, w = tid >> 5, lane = tid & 31;
    const int g = lane >> 2, tq = lane & 3;
    const int It = blockIdx.x, bh = blockIdx.y, h = bh & 7;
    const int rt = It * 128;
    const int ri5 = w >> 1;
    const int ra0 = (w & 1) * 16 + g;
    const __half* kbase = g_k + ((size_t)bh << 10) * 96;
    const __half* vbase = g_v + ((size_t)bh << 10) * 96;
    const float* tbase = g_table + h * 3969;

    const int lm_row = lane & 15;          // k row within 16
    const int lm_col = (lane >> 4) << 3;   // 0 or 8

    // prologue: Q + stage 0
    cpa_tile(sb, g_q + ((size_t)(bh << 10) + rt) * 96, tid);
    cpa_tile(sb + FL_KOFF(0), kbase, tid);
    cpa_tile(sb + FL_VOFF(0), vbase, tid);
    {
        const float* tg = tbase + (4 * It + 28) * 63;
        for (int i = tid; i < 441; i += 256) cpa4(sb + FL_TOFF(0) + i * 4, tg + i);
    }
    CP_COMMIT();

    float m0 = -1e30f, m1 = -1e30f, l0 = 0.f, l1 = 0.f;
    float oacc[11][4];
#pragma unroll
    for (int j = 0; j < 11; j++)
#pragma unroll
        for (int e = 0; e < 4; e++) oacc[j][e] = 0.f;

    const __half* Qs = (const __half*)smem;

#pragma unroll 1
    for (int nb = 0; nb < 8; nb++) {
        __syncthreads();
        if (nb < 7) {
            int s = (nb + 1) & 1;
            cpa_tile(sb + FL_KOFF(s), kbase + (size_t)(nb + 1) * 128 * 96, tid);
            cpa_tile(sb + FL_VOFF(s), vbase + (size_t)(nb + 1) * 128 * 96, tid);
            const float* tg = tbase + (4 * (It - nb - 1) + 28) * 63;
            for (int i = tid; i < 441; i += 256) cpa4(sb + FL_TOFF(s) + i * 4, tg + i);
            CP_COMMIT();
            asm volatile("cp.async.wait_group 1;" ::: "memory");
        } else {
            asm volatile("cp.async.wait_group 0;" ::: "memory");
        }
        __syncthreads();

        const __half* Ks = (const __half*)(smem + FL_KOFF(nb & 1));
        const uint32_t vsb = sb + FL_VOFF(nb & 1);
        const float* tabs = (const float*)(smem + FL_TOFF(nb & 1));

        // ---- S = Q K^T ----
        float sacc[16][4];
#pragma unroll
        for (int j = 0; j < 16; j++)
#pragma unroll
            for (int e = 0; e < 4; e++) sacc[j][e] = 0.f;

#pragma unroll
        for (int ks = 0; ks < 6; ks++) {
            int k0 = ks * 16;
            int r = w * 16 + g;
            const uint32_t* p0 = (const uint32_t*)&Qs[r * 104 + k0];
            const uint32_t* p1 = (const uint32_t*)&Qs[(r + 8) * 104 + k0];
            uint32_t a0 = p0[tq], a1 = p1[tq], a2 = p0[tq + 4], a3 = p1[tq + 4];
#pragma unroll
            for (int j = 0; j < 16; j++) {
                const uint32_t* pb = (const uint32_t*)&Ks[(j * 8 + g) * 104 + k0];
                mma16816(sacc[j], a0, a1, a2, a3, pb[tq], pb[tq + 4]);
            }
        }

        // ---- bias + row max ----
        float rmax0 = -1e30f, rmax1 = -1e30f;
#pragma unroll
        for (int j = 0; j < 16; j++) {
            int jl = j * 8 + 2 * tq;
            int rj5 = jl >> 5, cj = jl & 31;
            int dR0 = (ri5 - rj5 + 3) * 63;
            sacc[j][0] += tabs[dR0 + ra0 - cj + 31];
            sacc[j][1] += tabs[dR0 + ra0 - cj + 30];
            sacc[j][2] += tabs[dR0 + ra0 + 8 - cj + 31];
            sacc[j][3] += tabs[dR0 + ra0 + 8 - cj + 30];
            rmax0 = fmaxf(rmax0, fmaxf(sacc[j][0], sacc[j][1]));
            rmax1 = fmaxf(rmax1, fmaxf(sacc[j][2], sacc[j][3]));
        }
        rmax0 = fmaxf(rmax0, __shfl_xor_sync(0xffffffffu, rmax0, 1));
        rmax0 = fmaxf(rmax0, __shfl_xor_sync(0xffffffffu, rmax0, 2));
        rmax1 = fmaxf(rmax1, __shfl_xor_sync(0xffffffffu, rmax1, 1));
        rmax1 = fmaxf(rmax1, __shfl_xor_sync(0xffffffffu, rmax1, 2));

        // ---- online rescale ----
        float mn0 = fmaxf(m0, rmax0), mn1 = fmaxf(m1, rmax1);
        float al0 = __expf(m0 - mn0), al1 = __expf(m1 - mn1);
        m0 = mn0; m1 = mn1;
        float ls0 = 0.f, ls1 = 0.f;
#pragma unroll
        for (int j = 0; j < 16; j++) {
            sacc[j][0] = __expf(sacc[j][0] - mn0);
            sacc[j][1] = __expf(sacc[j][1] - mn0);
            sacc[j][2] = __expf(sacc[j][2] - mn1);
            sacc[j][3] = __expf(sacc[j][3] - mn1);
            ls0 += sacc[j][0] + sacc[j][1];
            ls1 += sacc[j][2] + sacc[j][3];
        }
        l0 = l0 * al0 + ls0;
        l1 = l1 * al1 + ls1;
#pragma unroll
        for (int j = 0; j < 11; j++) {
            oacc[j][0] *= al0; oacc[j][1] *= al0;
            oacc[j][2] *= al1; oacc[j][3] *= al1;
        }

        // ---- O += P V  (V fragments via ldmatrix.trans from [n][d] tile) ----
#pragma unroll
        for (int kk = 0; kk < 8; kk++) {
            __half2 h0 = __float22half2_rn(make_float2(sacc[2 * kk][0], sacc[2 * kk][1]));
            __half2 h1 = __float22half2_rn(make_float2(sacc[2 * kk][2], sacc[2 * kk][3]));
            __half2 h2 = __float22half2_rn(make_float2(sacc[2 * kk + 1][0], sacc[2 * kk + 1][1]));
            __half2 h3 = __float22half2_rn(make_float2(sacc[2 * kk + 1][2], sacc[2 * kk + 1][3]));
            uint32_t a0 = *(uint32_t*)&h0, a1 = *(uint32_t*)&h1;
            uint32_t a2 = *(uint32_t*)&h2, a3 = *(uint32_t*)&h3;
            int k0 = kk * 16;
            uint32_t rowaddr = vsb + (uint32_t)((k0 + lm_row) * 208);
#pragma unroll
            for (int jj = 0; jj < 6; jj++) {
                uint32_t r0, r1, r2, r3;
                uint32_t a = rowaddr + (uint32_t)((jj * 16 + lm_col) * 2);
                asm volatile(
                    "ldmatrix.sync.aligned.m8n8.x4.trans.shared.b16 {%0,%1,%2,%3}, [%4];"
                    : "=r"(r0), "=r"(r1), "=r"(r2), "=r"(r3) : "r"(a));
                mma16816(oacc[2 * jj], a0, a1, a2, a3, r0, r1);
                if (jj < 5) mma16816(oacc[2 * jj + 1], a0, a1, a2, a3, r2, r3);
            }
        }
    }

    // ---- epilogue ----
    l0 += __shfl_xor_sync(0xffffffffu, l0, 1);
    l0 += __shfl_xor_sync(0xffffffffu, l0, 2);
    l1 += __shfl_xor_sync(0xffffffffu, l1, 1);
    l1 += __shfl_xor_sync(0xffffffffu, l1, 2);
    float inv0 = 1.f / l0, inv1 = 1.f / l1;
    int b = bh >> 3;
    int row0 = rt + w * 16 + g, row1 = row0 + 8;
#pragma unroll
    for (int j = 0; j < 11; j++) {
        int d = j * 8 + 2 * tq;
        if (d < DD) {
            int m = d >> 2, c = d & 3;
            size_t o0 = ((size_t)((b << 10) + row0) * 21 + m) * 32 + (h << 2) + c;
            size_t o1 = ((size_t)((b << 10) + row1) * 21 + m) * 32 + (h << 2) + c;
            *(float2*)&g_opre[o0] = make_float2(oacc[j][0] * inv0, oacc[j][1] * inv0);
            *(float2*)&g_opre[o1] = make_float2(oacc[j][2] * inv1, oacc[j][3] * inv1);
        }
    }
}

// ---------------------------------------------------------------------------
// K7: out = opre @ W_proj + b_proj
// ---------------------------------------------------------------------------
__global__ void k_proj(const float* __restrict__ Wp, const float* __restrict__ bp,
                       float* __restrict__ out) {
    __shared__ float xs[32][33];
    __shared__ float ws[32][32];
    __shared__ float bs[32];
    int t = threadIdx.x;
    int row0 = blockIdx.x * 32;
    for (int i = t; i < 1024; i += 256) ws[i >> 5][i & 31] = Wp[i];
    if (t < 32) bs[t] = bp[t];
    for (int i = t; i < 1024; i += 256) xs[i >> 5][i & 31] = g_opre[(size_t)row0 * 32 + i];
    __syncthreads();
    for (int idx = t; idx < 1024; idx += 256) {
        int r = idx >> 5, j = idx & 31;
        float acc = bs[j];
#pragma unroll
        for (int kk = 0; kk < 32; kk++) acc += xs[r][kk] * ws[kk][j];
        out[(size_t)(row0 + r) * 32 + j] = acc;
    }
}

// ---------------------------------------------------------------------------
extern "C" void kernel_launch(void* const* d_in, const int* in_sizes, int n_in,
                              void* d_out, int out_size) {
    (void)in_sizes; (void)n_in; (void)out_size;
    const float* x   = (const float*)d_in[0];
    const float* Wq  = (const float*)d_in[1];
    const float* bq  = (const float*)d_in[2];
    const float* Wp  = (const float*)d_in[3];
    const float* bp  = (const float*)d_in[4];
    const float* Wsq = (const float*)d_in[5];
    const float* bsq = (const float*)d_in[6];
    const float* Wdw = (const float*)d_in[7];
    const float* bdw = (const float*)d_in[8];
    float* out = (float*)d_out;

    static int init_done = 0;
    if (!init_done) {
        cudaFuncSetAttribute(k_flash, cudaFuncAttributeMaxDynamicSharedMemorySize, FL_SMEM);
        init_done = 1;
    }

    k_qkv<<<4096, 128>>>(x, Wq, bq);
    k_x2<<<(BH * NN) / 256, 256>>>(x, Wsq, bsq);
    k_pool<<<BH, 256>>>();
    k_spatial_p<<<64, 256>>>(Wdw);
    k_table<<<NHH, 256>>>(bdw);
    k_flash<<<dim3(8, BH), 256, FL_SMEM>>>();
    k_proj<<<ROWS / 32, 256>>>(Wp, bp, out);
}